// round 1
// baseline (speedup 1.0000x reference)
#include <cuda_runtime.h>

// Problem constants
#define BB 4
#define TT 1024
#define DD 1024
#define HH 16
#define DH 64
#define BT (BB*TT)   // 4096

// Scratch (allocation-free: __device__ globals)
__device__ float g_Q[BB*TT*DD];                 // 16 MB
__device__ float g_K[BB*TT*DD];                 // 16 MB
__device__ float g_V[BB*TT*DD];                 // 16 MB
__device__ float g_A[(size_t)BB*HH*TT*TT];      // 256 MB attn matrix

// ---------------------------------------------------------------------------
// Kernel 1: projection GEMM  C(4096x1024) = X(4096x1024) @ W(1024x1024) + bias
// 64x64 tile, BK=16, 256 threads, 4x4 per thread.
// ---------------------------------------------------------------------------
__global__ __launch_bounds__(256) void proj_kernel(
    const float* __restrict__ X, const float* __restrict__ W,
    const float* __restrict__ bias, float* __restrict__ C)
{
    __shared__ float As[16][64];   // [k][m]
    __shared__ float Bs[16][64];   // [k][n]

    const int tid = threadIdx.x;
    const int tx = tid & 15;
    const int ty = tid >> 4;
    const int row0 = blockIdx.y * 64;
    const int col0 = blockIdx.x * 64;

    const int a_row = tid >> 2;           // 0..63
    const int a_col = (tid & 3) * 4;      // 0,4,8,12
    const int b_row = tid >> 4;           // 0..15
    const int b_col = (tid & 15) * 4;     // 0..60

    float acc[4][4] = {};

    for (int k0 = 0; k0 < DD; k0 += 16) {
        float4 av = *reinterpret_cast<const float4*>(&X[(size_t)(row0 + a_row) * DD + k0 + a_col]);
        As[a_col + 0][a_row] = av.x;
        As[a_col + 1][a_row] = av.y;
        As[a_col + 2][a_row] = av.z;
        As[a_col + 3][a_row] = av.w;
        *reinterpret_cast<float4*>(&Bs[b_row][b_col]) =
            *reinterpret_cast<const float4*>(&W[(size_t)(k0 + b_row) * DD + col0 + b_col]);
        __syncthreads();

        #pragma unroll
        for (int k = 0; k < 16; k++) {
            float4 a = *reinterpret_cast<const float4*>(&As[k][ty * 4]);
            float4 b = *reinterpret_cast<const float4*>(&Bs[k][tx * 4]);
            acc[0][0] += a.x * b.x; acc[0][1] += a.x * b.y; acc[0][2] += a.x * b.z; acc[0][3] += a.x * b.w;
            acc[1][0] += a.y * b.x; acc[1][1] += a.y * b.y; acc[1][2] += a.y * b.z; acc[1][3] += a.y * b.w;
            acc[2][0] += a.z * b.x; acc[2][1] += a.z * b.y; acc[2][2] += a.z * b.z; acc[2][3] += a.z * b.w;
            acc[3][0] += a.w * b.x; acc[3][1] += a.w * b.y; acc[3][2] += a.w * b.z; acc[3][3] += a.w * b.w;
        }
        __syncthreads();
    }

    #pragma unroll
    for (int i = 0; i < 4; i++) {
        const int r = row0 + ty * 4 + i;
        #pragma unroll
        for (int j = 0; j < 4; j++) {
            const int c = col0 + tx * 4 + j;
            C[(size_t)r * DD + c] = acc[i][j] + bias[c];
        }
    }
}

// ---------------------------------------------------------------------------
// Kernel 2: attn[b,h,t,s] = temp[h] * sum_d Kh[d,t] * Vh[d,s]
// Kh/Vh = 64-row blocks of g_K / g_V.  Per block: 64x64 output tile, K-dim=64.
// ---------------------------------------------------------------------------
__global__ __launch_bounds__(256) void attn_kernel(const float* __restrict__ temperature)
{
    __shared__ float Ks[64][64];   // [d][t]
    __shared__ float Vs[64][64];   // [d][s]

    const int tid = threadIdx.x;
    const int tx = tid & 15;
    const int ty = tid >> 4;
    const int bh = blockIdx.z;
    const int b  = bh >> 4;
    const int h  = bh & 15;
    const int t0 = blockIdx.y * 64;
    const int s0 = blockIdx.x * 64;

    const float* Kh = g_K + (size_t)b * TT * DD + (size_t)(h * DH) * DD;
    const float* Vh = g_V + (size_t)b * TT * DD + (size_t)(h * DH) * DD;

    const int lr = tid >> 4;           // 0..15
    const int lc = (tid & 15) * 4;     // 0..60

    #pragma unroll
    for (int i = 0; i < 4; i++) {
        const int d = lr + i * 16;
        *reinterpret_cast<float4*>(&Ks[d][lc]) =
            *reinterpret_cast<const float4*>(&Kh[(size_t)d * DD + t0 + lc]);
        *reinterpret_cast<float4*>(&Vs[d][lc]) =
            *reinterpret_cast<const float4*>(&Vh[(size_t)d * DD + s0 + lc]);
    }
    __syncthreads();

    float acc[4][4] = {};
    #pragma unroll 8
    for (int d = 0; d < 64; d++) {
        float4 a = *reinterpret_cast<const float4*>(&Ks[d][ty * 4]);
        float4 v = *reinterpret_cast<const float4*>(&Vs[d][tx * 4]);
        acc[0][0] += a.x * v.x; acc[0][1] += a.x * v.y; acc[0][2] += a.x * v.z; acc[0][3] += a.x * v.w;
        acc[1][0] += a.y * v.x; acc[1][1] += a.y * v.y; acc[1][2] += a.y * v.z; acc[1][3] += a.y * v.w;
        acc[2][0] += a.z * v.x; acc[2][1] += a.z * v.y; acc[2][2] += a.z * v.z; acc[2][3] += a.z * v.w;
        acc[3][0] += a.w * v.x; acc[3][1] += a.w * v.y; acc[3][2] += a.w * v.z; acc[3][3] += a.w * v.w;
    }

    const float tmp = temperature[h];
    float* Abase = g_A + ((size_t)bh * TT + t0) * TT + s0;
    #pragma unroll
    for (int i = 0; i < 4; i++) {
        #pragma unroll
        for (int j = 0; j < 4; j++) {
            Abase[(size_t)(ty * 4 + i) * TT + tx * 4 + j] = acc[i][j] * tmp;
        }
    }
}

// ---------------------------------------------------------------------------
// Kernel 3: row softmax over last dim of g_A.  One warp per 1024-elem row.
// ---------------------------------------------------------------------------
__global__ __launch_bounds__(256) void softmax_kernel()
{
    const int warp_in_block = threadIdx.x >> 5;
    const int lane = threadIdx.x & 31;
    const size_t row = (size_t)blockIdx.x * 8 + warp_in_block;   // 65536 rows total

    float* rp = g_A + row * TT;

    float vals[32];
    float mx = -3.402823466e+38f;
    #pragma unroll
    for (int i = 0; i < 8; i++) {
        float4 v = *reinterpret_cast<const float4*>(&rp[(i * 32 + lane) * 4]);
        vals[i * 4 + 0] = v.x; vals[i * 4 + 1] = v.y;
        vals[i * 4 + 2] = v.z; vals[i * 4 + 3] = v.w;
        mx = fmaxf(mx, fmaxf(fmaxf(v.x, v.y), fmaxf(v.z, v.w)));
    }
    #pragma unroll
    for (int off = 16; off > 0; off >>= 1)
        mx = fmaxf(mx, __shfl_xor_sync(0xffffffffu, mx, off));

    float sum = 0.f;
    #pragma unroll
    for (int i = 0; i < 32; i++) {
        vals[i] = __expf(vals[i] - mx);
        sum += vals[i];
    }
    #pragma unroll
    for (int off = 16; off > 0; off >>= 1)
        sum += __shfl_xor_sync(0xffffffffu, sum, off);

    const float inv = 1.0f / sum;
    #pragma unroll
    for (int i = 0; i < 8; i++) {
        float4 v;
        v.x = vals[i * 4 + 0] * inv; v.y = vals[i * 4 + 1] * inv;
        v.z = vals[i * 4 + 2] * inv; v.w = vals[i * 4 + 3] * inv;
        *reinterpret_cast<float4*>(&rp[(i * 32 + lane) * 4]) = v;
    }
}

// ---------------------------------------------------------------------------
// Kernel 4: out rows [h*64, h*64+64) of batch b = Qh(64x1024) @ A_bh(1024x1024)
// ---------------------------------------------------------------------------
__global__ __launch_bounds__(256) void out_kernel(float* __restrict__ out)
{
    __shared__ float Qs[16][64];   // [k][m]
    __shared__ float Ps[16][64];   // [k][n]

    const int tid = threadIdx.x;
    const int tx = tid & 15;
    const int ty = tid >> 4;
    const int bh = blockIdx.z;
    const int b  = bh >> 4;
    const int h  = bh & 15;
    const int s0 = blockIdx.x * 64;

    const float* Qh  = g_Q + (size_t)b * TT * DD + (size_t)(h * DH) * DD;   // 64 x 1024
    const float* Abh = g_A + (size_t)bh * TT * TT;                          // 1024 x 1024

    const int a_row = tid >> 2;           // 0..63 (dd)
    const int a_col = (tid & 3) * 4;      // 0,4,8,12
    const int b_row = tid >> 4;           // 0..15 (k)
    const int b_col = (tid & 15) * 4;

    float acc[4][4] = {};

    for (int k0 = 0; k0 < TT; k0 += 16) {
        float4 av = *reinterpret_cast<const float4*>(&Qh[(size_t)a_row * DD + k0 + a_col]);
        Qs[a_col + 0][a_row] = av.x;
        Qs[a_col + 1][a_row] = av.y;
        Qs[a_col + 2][a_row] = av.z;
        Qs[a_col + 3][a_row] = av.w;
        *reinterpret_cast<float4*>(&Ps[b_row][b_col]) =
            *reinterpret_cast<const float4*>(&Abh[(size_t)(k0 + b_row) * TT + s0 + b_col]);
        __syncthreads();

        #pragma unroll
        for (int k = 0; k < 16; k++) {
            float4 a = *reinterpret_cast<const float4*>(&Qs[k][ty * 4]);
            float4 p = *reinterpret_cast<const float4*>(&Ps[k][tx * 4]);
            acc[0][0] += a.x * p.x; acc[0][1] += a.x * p.y; acc[0][2] += a.x * p.z; acc[0][3] += a.x * p.w;
            acc[1][0] += a.y * p.x; acc[1][1] += a.y * p.y; acc[1][2] += a.y * p.z; acc[1][3] += a.y * p.w;
            acc[2][0] += a.z * p.x; acc[2][1] += a.z * p.y; acc[2][2] += a.z * p.z; acc[2][3] += a.z * p.w;
            acc[3][0] += a.w * p.x; acc[3][1] += a.w * p.y; acc[3][2] += a.w * p.z; acc[3][3] += a.w * p.w;
        }
        __syncthreads();
    }

    // out[b, h*64+dd, s]
    float* orow = out + (size_t)b * TT * DD + (size_t)(h * DH) * DD;
    #pragma unroll
    for (int i = 0; i < 4; i++) {
        #pragma unroll
        for (int j = 0; j < 4; j++) {
            orow[(size_t)(ty * 4 + i) * DD + s0 + tx * 4 + j] = acc[i][j];
        }
    }
}

// ---------------------------------------------------------------------------
extern "C" void kernel_launch(void* const* d_in, const int* in_sizes, int n_in,
                              void* d_out, int out_size)
{
    const float* x    = (const float*)d_in[0];
    const float* Wq   = (const float*)d_in[1];
    const float* bq   = (const float*)d_in[2];
    const float* Wk   = (const float*)d_in[3];
    const float* bk   = (const float*)d_in[4];
    const float* Wv   = (const float*)d_in[5];
    const float* bv   = (const float*)d_in[6];
    const float* temp = (const float*)d_in[7];
    float* out = (float*)d_out;

    static float* Qp = nullptr;
    static float* Kp = nullptr;
    static float* Vp = nullptr;
    if (!Qp) {
        cudaGetSymbolAddress((void**)&Qp, g_Q);
        cudaGetSymbolAddress((void**)&Kp, g_K);
        cudaGetSymbolAddress((void**)&Vp, g_V);
    }

    dim3 pgrid(DD / 64, BT / 64);          // 16 x 64
    proj_kernel<<<pgrid, 256>>>(x, Wq, bq, Qp);
    proj_kernel<<<pgrid, 256>>>(x, Wk, bk, Kp);
    proj_kernel<<<pgrid, 256>>>(x, Wv, bv, Vp);

    dim3 agrid(TT / 64, TT / 64, BB * HH); // 16 x 16 x 64
    attn_kernel<<<agrid, 256>>>(temp);

    softmax_kernel<<<(BB * HH * TT) / 8, 256>>>();

    dim3 ogrid(TT / 64, 1, BB * HH);       // 16 x 1 x 64
    out_kernel<<<ogrid, 256>>>(out);
}

// round 2
// speedup vs baseline: 1.0306x; 1.0306x over previous
#include <cuda_runtime.h>

// Problem constants
#define BB 4
#define TT 1024
#define DD 1024
#define HH 16
#define DH 64
#define BT (BB*TT)   // 4096

// Scratch (allocation-free: __device__ globals)
__device__ float g_Q[BB*TT*DD];                 // 16 MB
__device__ float g_K[BB*TT*DD];                 // 16 MB
__device__ float g_V[BB*TT*DD];                 // 16 MB
__device__ float g_A[(size_t)BB*HH*TT*TT];      // 256 MB attn matrix

// ---------------------------------------------------------------------------
// Packed f32x2 helpers (FFMA2: 2 FMAs per issue slot; PTX-only pattern)
// ---------------------------------------------------------------------------
__device__ __forceinline__ unsigned long long pack2(float lo, float hi) {
    unsigned long long r;
    asm("mov.b64 %0, {%1, %2};" : "=l"(r) : "f"(lo), "f"(hi));
    return r;
}
__device__ __forceinline__ unsigned long long dup2(float v) {
    unsigned long long r;
    asm("mov.b64 %0, {%1, %1};" : "=l"(r) : "f"(v));
    return r;
}
__device__ __forceinline__ void ffma2(unsigned long long& d,
                                      unsigned long long a,
                                      unsigned long long b) {
    asm("fma.rn.f32x2 %0, %1, %2, %0;" : "+l"(d) : "l"(a), "l"(b));
}
__device__ __forceinline__ float2 unpack2(unsigned long long v) {
    float2 r;
    asm("mov.b64 {%0, %1}, %2;" : "=f"(r.x), "=f"(r.y) : "l"(v));
    return r;
}

// ---------------------------------------------------------------------------
// Kernel 1: projection GEMM  C(4096x1024) = X(4096x1024) @ W(1024x1024) + bias
// 128x128 tile, BK=16, 256 threads, 8x8 per thread via FFMA2.
// ---------------------------------------------------------------------------
__global__ __launch_bounds__(256) void proj_kernel(
    const float* __restrict__ X, const float* __restrict__ W,
    const float* __restrict__ bias, float* __restrict__ C)
{
    __shared__ float As[16][128];   // [k][m]
    __shared__ float Bs[16][128];   // [k][n]

    const int tid = threadIdx.x;
    const int tx = tid & 15;        // n-group
    const int ty = tid >> 4;        // m-group
    const int row0 = blockIdx.y * 128;
    const int col0 = blockIdx.x * 128;

    const int ar = tid >> 1;          // 0..127
    const int ac = (tid & 1) * 8;     // 0 or 8
    const int br = tid >> 4;          // 0..15
    const int bc = (tid & 15) * 8;    // 0..120

    unsigned long long acc[4][8] = {};   // rows pairs (2ip,2ip+1), col j

    for (int k0 = 0; k0 < DD; k0 += 16) {
        float4 av0 = *reinterpret_cast<const float4*>(&X[(size_t)(row0 + ar) * DD + k0 + ac]);
        float4 av1 = *reinterpret_cast<const float4*>(&X[(size_t)(row0 + ar) * DD + k0 + ac + 4]);
        As[ac + 0][ar] = av0.x; As[ac + 1][ar] = av0.y;
        As[ac + 2][ar] = av0.z; As[ac + 3][ar] = av0.w;
        As[ac + 4][ar] = av1.x; As[ac + 5][ar] = av1.y;
        As[ac + 6][ar] = av1.z; As[ac + 7][ar] = av1.w;
        *reinterpret_cast<float4*>(&Bs[br][bc]) =
            *reinterpret_cast<const float4*>(&W[(size_t)(k0 + br) * DD + col0 + bc]);
        *reinterpret_cast<float4*>(&Bs[br][bc + 4]) =
            *reinterpret_cast<const float4*>(&W[(size_t)(k0 + br) * DD + col0 + bc + 4]);
        __syncthreads();

        #pragma unroll
        for (int k = 0; k < 16; k++) {
            float4 a0 = *reinterpret_cast<const float4*>(&As[k][ty * 8]);
            float4 a1 = *reinterpret_cast<const float4*>(&As[k][ty * 8 + 4]);
            float4 b0 = *reinterpret_cast<const float4*>(&Bs[k][tx * 8]);
            float4 b1 = *reinterpret_cast<const float4*>(&Bs[k][tx * 8 + 4]);
            unsigned long long a2[4] = {pack2(a0.x, a0.y), pack2(a0.z, a0.w),
                                        pack2(a1.x, a1.y), pack2(a1.z, a1.w)};
            unsigned long long bb[8] = {dup2(b0.x), dup2(b0.y), dup2(b0.z), dup2(b0.w),
                                        dup2(b1.x), dup2(b1.y), dup2(b1.z), dup2(b1.w)};
            #pragma unroll
            for (int ip = 0; ip < 4; ip++)
                #pragma unroll
                for (int j = 0; j < 8; j++)
                    ffma2(acc[ip][j], a2[ip], bb[j]);
        }
        __syncthreads();
    }

    float4 bv0 = *reinterpret_cast<const float4*>(&bias[col0 + tx * 8]);
    float4 bv1 = *reinterpret_cast<const float4*>(&bias[col0 + tx * 8 + 4]);
    const float bj[8] = {bv0.x, bv0.y, bv0.z, bv0.w, bv1.x, bv1.y, bv1.z, bv1.w};

    #pragma unroll
    for (int ip = 0; ip < 4; ip++) {
        float r0[8], r1[8];
        #pragma unroll
        for (int j = 0; j < 8; j++) {
            float2 v = unpack2(acc[ip][j]);
            r0[j] = v.x + bj[j];
            r1[j] = v.y + bj[j];
        }
        float* p0 = &C[(size_t)(row0 + ty * 8 + 2 * ip) * DD + col0 + tx * 8];
        float* p1 = p0 + DD;
        *reinterpret_cast<float4*>(p0)     = make_float4(r0[0], r0[1], r0[2], r0[3]);
        *reinterpret_cast<float4*>(p0 + 4) = make_float4(r0[4], r0[5], r0[6], r0[7]);
        *reinterpret_cast<float4*>(p1)     = make_float4(r1[0], r1[1], r1[2], r1[3]);
        *reinterpret_cast<float4*>(p1 + 4) = make_float4(r1[4], r1[5], r1[6], r1[7]);
    }
}

// ---------------------------------------------------------------------------
// Kernel 2: attn[b,h,t,s] = temp[h] * sum_d Kh[d,t] * Vh[d,s]
// 128x128 output tile, K-dim=64 fully staged in smem (64 KB dynamic), FFMA2.
// ---------------------------------------------------------------------------
__global__ __launch_bounds__(256) void attn_kernel(const float* __restrict__ temperature)
{
    extern __shared__ float sm[];
    float (*Ks)[128] = reinterpret_cast<float (*)[128]>(sm);          // [d][t]
    float (*Vs)[128] = reinterpret_cast<float (*)[128]>(sm + 64*128); // [d][s]

    const int tid = threadIdx.x;
    const int tx = tid & 15;
    const int ty = tid >> 4;
    const int bh = blockIdx.z;
    const int b  = bh >> 4;
    const int h  = bh & 15;
    const int t0 = blockIdx.y * 128;
    const int s0 = blockIdx.x * 128;

    const float* Kh = g_K + (size_t)b * TT * DD + (size_t)(h * DH) * DD;
    const float* Vh = g_V + (size_t)b * TT * DD + (size_t)(h * DH) * DD;

    #pragma unroll
    for (int i = 0; i < 8; i++) {
        const int idx = i * 256 + tid;
        const int d  = idx >> 5;          // 0..63
        const int c4 = (idx & 31) * 4;    // 0..124
        *reinterpret_cast<float4*>(&Ks[d][c4]) =
            *reinterpret_cast<const float4*>(&Kh[(size_t)d * DD + t0 + c4]);
        *reinterpret_cast<float4*>(&Vs[d][c4]) =
            *reinterpret_cast<const float4*>(&Vh[(size_t)d * DD + s0 + c4]);
    }
    __syncthreads();

    unsigned long long acc[4][8] = {};

    #pragma unroll 8
    for (int d = 0; d < 64; d++) {
        float4 a0 = *reinterpret_cast<const float4*>(&Ks[d][ty * 8]);
        float4 a1 = *reinterpret_cast<const float4*>(&Ks[d][ty * 8 + 4]);
        float4 b0 = *reinterpret_cast<const float4*>(&Vs[d][tx * 8]);
        float4 b1 = *reinterpret_cast<const float4*>(&Vs[d][tx * 8 + 4]);
        unsigned long long a2[4] = {pack2(a0.x, a0.y), pack2(a0.z, a0.w),
                                    pack2(a1.x, a1.y), pack2(a1.z, a1.w)};
        unsigned long long bb[8] = {dup2(b0.x), dup2(b0.y), dup2(b0.z), dup2(b0.w),
                                    dup2(b1.x), dup2(b1.y), dup2(b1.z), dup2(b1.w)};
        #pragma unroll
        for (int ip = 0; ip < 4; ip++)
            #pragma unroll
            for (int j = 0; j < 8; j++)
                ffma2(acc[ip][j], a2[ip], bb[j]);
    }

    const float tmp = temperature[h];
    float* Abase = g_A + ((size_t)bh * TT + t0) * TT + s0;
    #pragma unroll
    for (int ip = 0; ip < 4; ip++) {
        float r0[8], r1[8];
        #pragma unroll
        for (int j = 0; j < 8; j++) {
            float2 v = unpack2(acc[ip][j]);
            r0[j] = v.x * tmp;
            r1[j] = v.y * tmp;
        }
        float* p0 = &Abase[(size_t)(ty * 8 + 2 * ip) * TT + tx * 8];
        float* p1 = p0 + TT;
        *reinterpret_cast<float4*>(p0)     = make_float4(r0[0], r0[1], r0[2], r0[3]);
        *reinterpret_cast<float4*>(p0 + 4) = make_float4(r0[4], r0[5], r0[6], r0[7]);
        *reinterpret_cast<float4*>(p1)     = make_float4(r1[0], r1[1], r1[2], r1[3]);
        *reinterpret_cast<float4*>(p1 + 4) = make_float4(r1[4], r1[5], r1[6], r1[7]);
    }
}

// ---------------------------------------------------------------------------
// Kernel 3: row softmax over last dim of g_A.  One warp per 1024-elem row.
// ---------------------------------------------------------------------------
__global__ __launch_bounds__(256) void softmax_kernel()
{
    const int warp_in_block = threadIdx.x >> 5;
    const int lane = threadIdx.x & 31;
    const size_t row = (size_t)blockIdx.x * 8 + warp_in_block;   // 65536 rows total

    float* rp = g_A + row * TT;

    float vals[32];
    float mx = -3.402823466e+38f;
    #pragma unroll
    for (int i = 0; i < 8; i++) {
        float4 v = *reinterpret_cast<const float4*>(&rp[(i * 32 + lane) * 4]);
        vals[i * 4 + 0] = v.x; vals[i * 4 + 1] = v.y;
        vals[i * 4 + 2] = v.z; vals[i * 4 + 3] = v.w;
        mx = fmaxf(mx, fmaxf(fmaxf(v.x, v.y), fmaxf(v.z, v.w)));
    }
    #pragma unroll
    for (int off = 16; off > 0; off >>= 1)
        mx = fmaxf(mx, __shfl_xor_sync(0xffffffffu, mx, off));

    float sum = 0.f;
    #pragma unroll
    for (int i = 0; i < 32; i++) {
        vals[i] = __expf(vals[i] - mx);
        sum += vals[i];
    }
    #pragma unroll
    for (int off = 16; off > 0; off >>= 1)
        sum += __shfl_xor_sync(0xffffffffu, sum, off);

    const float inv = 1.0f / sum;
    #pragma unroll
    for (int i = 0; i < 8; i++) {
        float4 v;
        v.x = vals[i * 4 + 0] * inv; v.y = vals[i * 4 + 1] * inv;
        v.z = vals[i * 4 + 2] * inv; v.w = vals[i * 4 + 3] * inv;
        *reinterpret_cast<float4*>(&rp[(i * 32 + lane) * 4]) = v;
    }
}

// ---------------------------------------------------------------------------
// Kernel 4: out rows [h*64, h*64+64) of batch b = Qh(64x1024) @ A_bh(1024x1024)
// 64x128 tile, BK=32, 256 threads, 4x8 per thread via FFMA2.
// ---------------------------------------------------------------------------
__global__ __launch_bounds__(256) void out_kernel(float* __restrict__ out)
{
    __shared__ float Qs[32][68];    // [k][m], padded to reduce store conflicts
    __shared__ float Ps[32][128];   // [k][n]

    const int tid = threadIdx.x;
    const int tx = tid & 15;        // n-group: cols tx*8..+8
    const int ty = tid >> 4;        // m-group: rows ty*4..+4
    const int bh = blockIdx.z;
    const int b  = bh >> 4;
    const int h  = bh & 15;
    const int s0 = blockIdx.x * 128;

    const float* Qh  = g_Q + (size_t)b * TT * DD + (size_t)(h * DH) * DD;   // 64 x 1024
    const float* Abh = g_A + (size_t)bh * TT * TT;                          // 1024 x 1024

    unsigned long long acc[2][8] = {};

    for (int k0 = 0; k0 < TT; k0 += 32) {
        #pragma unroll
        for (int i = 0; i < 2; i++) {
            const int idx = i * 256 + tid;
            const int r  = idx >> 3;          // 0..63
            const int c4 = (idx & 7) * 4;     // 0..28
            float4 q = *reinterpret_cast<const float4*>(&Qh[(size_t)r * DD + k0 + c4]);
            Qs[c4 + 0][r] = q.x; Qs[c4 + 1][r] = q.y;
            Qs[c4 + 2][r] = q.z; Qs[c4 + 3][r] = q.w;
        }
        #pragma unroll
        for (int i = 0; i < 4; i++) {
            const int idx = i * 256 + tid;
            const int r  = idx >> 5;          // 0..31
            const int c4 = (idx & 31) * 4;    // 0..124
            *reinterpret_cast<float4*>(&Ps[r][c4]) =
                *reinterpret_cast<const float4*>(&Abh[(size_t)(k0 + r) * TT + s0 + c4]);
        }
        __syncthreads();

        #pragma unroll
        for (int k = 0; k < 32; k++) {
            float4 a  = *reinterpret_cast<const float4*>(&Qs[k][ty * 4]);
            float4 b0 = *reinterpret_cast<const float4*>(&Ps[k][tx * 8]);
            float4 b1 = *reinterpret_cast<const float4*>(&Ps[k][tx * 8 + 4]);
            unsigned long long a2[2] = {pack2(a.x, a.y), pack2(a.z, a.w)};
            unsigned long long bb[8] = {dup2(b0.x), dup2(b0.y), dup2(b0.z), dup2(b0.w),
                                        dup2(b1.x), dup2(b1.y), dup2(b1.z), dup2(b1.w)};
            #pragma unroll
            for (int ip = 0; ip < 2; ip++)
                #pragma unroll
                for (int j = 0; j < 8; j++)
                    ffma2(acc[ip][j], a2[ip], bb[j]);
        }
        __syncthreads();
    }

    float* orow = out + (size_t)b * TT * DD + (size_t)(h * DH) * DD;
    #pragma unroll
    for (int ip = 0; ip < 2; ip++) {
        float r0[8], r1[8];
        #pragma unroll
        for (int j = 0; j < 8; j++) {
            float2 v = unpack2(acc[ip][j]);
            r0[j] = v.x;
            r1[j] = v.y;
        }
        float* p0 = &orow[(size_t)(ty * 4 + 2 * ip) * DD + s0 + tx * 8];
        float* p1 = p0 + DD;
        *reinterpret_cast<float4*>(p0)     = make_float4(r0[0], r0[1], r0[2], r0[3]);
        *reinterpret_cast<float4*>(p0 + 4) = make_float4(r0[4], r0[5], r0[6], r0[7]);
        *reinterpret_cast<float4*>(p1)     = make_float4(r1[0], r1[1], r1[2], r1[3]);
        *reinterpret_cast<float4*>(p1 + 4) = make_float4(r1[4], r1[5], r1[6], r1[7]);
    }
}

// ---------------------------------------------------------------------------
extern "C" void kernel_launch(void* const* d_in, const int* in_sizes, int n_in,
                              void* d_out, int out_size)
{
    const float* x    = (const float*)d_in[0];
    const float* Wq   = (const float*)d_in[1];
    const float* bq   = (const float*)d_in[2];
    const float* Wk   = (const float*)d_in[3];
    const float* bk   = (const float*)d_in[4];
    const float* Wv   = (const float*)d_in[5];
    const float* bv   = (const float*)d_in[6];
    const float* temp = (const float*)d_in[7];
    float* out = (float*)d_out;

    static float* Qp = nullptr;
    static float* Kp = nullptr;
    static float* Vp = nullptr;
    if (!Qp) {
        cudaGetSymbolAddress((void**)&Qp, g_Q);
        cudaGetSymbolAddress((void**)&Kp, g_K);
        cudaGetSymbolAddress((void**)&Vp, g_V);
        cudaFuncSetAttribute(attn_kernel,
                             cudaFuncAttributeMaxDynamicSharedMemorySize, 65536);
    }

    dim3 pgrid(DD / 128, BT / 128);          // 8 x 32
    proj_kernel<<<pgrid, 256>>>(x, Wq, bq, Qp);
    proj_kernel<<<pgrid, 256>>>(x, Wk, bk, Kp);
    proj_kernel<<<pgrid, 256>>>(x, Wv, bv, Vp);

    dim3 agrid(TT / 128, TT / 128, BB * HH); // 8 x 8 x 64
    attn_kernel<<<agrid, 256, 65536>>>(temp);

    softmax_kernel<<<(BB * HH * TT) / 8, 256>>>();

    dim3 ogrid(TT / 128, 1, BB * HH);        // 8 x 1 x 64
    out_kernel<<<ogrid, 256>>>(out);
}

// round 4
// speedup vs baseline: 1.1743x; 1.1394x over previous
#include <cuda_runtime.h>
#include <cstdint>

// Problem constants
#define BB 4
#define TT 1024
#define DD 1024
#define HH 16
#define DH 64
#define BT (BB*TT)   // 4096

// Scratch (allocation-free: __device__ globals)
__device__ float g_Q[BB*TT*DD];                 // 16 MB
__device__ float g_K[BB*TT*DD];                 // 16 MB
__device__ float g_V[BB*TT*DD];                 // 16 MB
__device__ float g_A[(size_t)BB*HH*TT*TT];      // 256 MB attn matrix
__device__ float g_Xhi[BT*DD];                  // 16 MB tf32-hi of x
__device__ float g_Xlo[BT*DD];                  // 16 MB tf32-lo of x
__device__ float g_Wthi[3][DD*DD];              // transposed W hi (12 MB)
__device__ float g_Wtlo[3][DD*DD];              // transposed W lo (12 MB)

// ---------------------------------------------------------------------------
// Helpers
// ---------------------------------------------------------------------------
__device__ __forceinline__ uint32_t smem_u32(const void* p) {
    uint32_t a;
    asm("{ .reg .u64 t; cvta.to.shared.u64 t, %1; cvt.u32.u64 %0, t; }" : "=r"(a) : "l"(p));
    return a;
}
__device__ __forceinline__ float to_tf32(float v) {
    uint32_t u;
    asm("cvt.rna.tf32.f32 %0, %1;" : "=r"(u) : "f"(v));
    return __uint_as_float(u);
}
__device__ __forceinline__ void cp16(uint32_t dst, const void* src) {
    asm volatile("cp.async.cg.shared.global [%0], [%1], 16;" :: "r"(dst), "l"(src));
}
#define CP_COMMIT() asm volatile("cp.async.commit_group;" ::: "memory")
#define CP_WAIT1()  asm volatile("cp.async.wait_group 1;" ::: "memory")
#define CP_WAIT0()  asm volatile("cp.async.wait_group 0;" ::: "memory")

#define MMA_TF32(d, a, b) \
    asm volatile("mma.sync.aligned.m16n8k8.row.col.f32.tf32.tf32.f32 " \
        "{%0,%1,%2,%3}, {%4,%5,%6,%7}, {%8,%9}, {%0,%1,%2,%3};" \
        : "+f"((d)[0]), "+f"((d)[1]), "+f"((d)[2]), "+f"((d)[3]) \
        : "r"((a)[0]), "r"((a)[1]), "r"((a)[2]), "r"((a)[3]), \
          "r"((b)[0]), "r"((b)[1]))

// ---------------------------------------------------------------------------
// Packed f32x2 helpers (FFMA2)
// ---------------------------------------------------------------------------
__device__ __forceinline__ unsigned long long pack2(float lo, float hi) {
    unsigned long long r;
    asm("mov.b64 %0, {%1, %2};" : "=l"(r) : "f"(lo), "f"(hi));
    return r;
}
__device__ __forceinline__ unsigned long long dup2(float v) {
    unsigned long long r;
    asm("mov.b64 %0, {%1, %1};" : "=l"(r) : "f"(v));
    return r;
}
__device__ __forceinline__ void ffma2(unsigned long long& d,
                                      unsigned long long a,
                                      unsigned long long b) {
    asm("fma.rn.f32x2 %0, %1, %2, %0;" : "+l"(d) : "l"(a), "l"(b));
}
__device__ __forceinline__ float2 unpack2(unsigned long long v) {
    float2 r;
    asm("mov.b64 {%0, %1}, %2;" : "=f"(r.x), "=f"(r.y) : "l"(v));
    return r;
}

// ---------------------------------------------------------------------------
// Prep 1: split X into tf32 hi/lo
// ---------------------------------------------------------------------------
__global__ __launch_bounds__(256) void split_x_kernel(const float* __restrict__ x)
{
    const size_t i4 = ((size_t)blockIdx.x * 256 + threadIdx.x) * 4;
    float4 v = *reinterpret_cast<const float4*>(&x[i4]);
    float4 h, l;
    h.x = to_tf32(v.x); l.x = to_tf32(v.x - h.x);
    h.y = to_tf32(v.y); l.y = to_tf32(v.y - h.y);
    h.z = to_tf32(v.z); l.z = to_tf32(v.z - h.z);
    h.w = to_tf32(v.w); l.w = to_tf32(v.w - h.w);
    *reinterpret_cast<float4*>(&g_Xhi[i4]) = h;
    *reinterpret_cast<float4*>(&g_Xlo[i4]) = l;
}

// ---------------------------------------------------------------------------
// Prep 2: transpose W (1024x1024) + tf32 hi/lo split: Wt[n][k] = W[k][n]
// ---------------------------------------------------------------------------
__global__ void wtrans_kernel(const float* __restrict__ W, int widx)
{
    __shared__ float s[32][33];
    const int tx = threadIdx.x;       // 0..31
    const int ty = threadIdx.y;       // 0..7
    const int k0 = blockIdx.x * 32;
    const int n0 = blockIdx.y * 32;

    #pragma unroll
    for (int i = 0; i < 4; i++)
        s[ty + i * 8][tx] = W[(size_t)(k0 + ty + i * 8) * DD + n0 + tx];
    __syncthreads();

    float* hi = g_Wthi[widx];
    float* lo = g_Wtlo[widx];
    #pragma unroll
    for (int i = 0; i < 4; i++) {
        float v = s[tx][ty + i * 8];
        float h = to_tf32(v);
        hi[(size_t)(n0 + ty + i * 8) * DD + k0 + tx] = h;
        lo[(size_t)(n0 + ty + i * 8) * DD + k0 + tx] = to_tf32(v - h);
    }
}

// ---------------------------------------------------------------------------
// Kernel 1: projection GEMM via mma.sync m16n8k8 tf32, 3xTF32 hi/lo split.
// C(4096x1024) = X @ W + bias.
// Block tile 128x128, BK=32, 256 threads (8 warps, warp tile 32x64),
// cp.async double-buffered.  Smem rows padded to 36 floats (conflict-free).
// ---------------------------------------------------------------------------
#define ROWPAD 36
#define MAT_F  (128 * ROWPAD)        // floats per matrix per stage (4608)
#define STG_F  (4 * MAT_F)           // floats per stage (18432)
#define PROJ_SMEM (2 * STG_F * 4)    // bytes = 147456
#define NCHUNK 32                    // 1024 / BK32

__global__ __launch_bounds__(256, 1) void proj_mma_kernel(
    const float* __restrict__ Ahi_g, const float* __restrict__ Alo_g,
    const float* __restrict__ Bhi_g, const float* __restrict__ Blo_g,
    const float* __restrict__ bias, float* __restrict__ C)
{
    extern __shared__ float sm[];
    const uint32_t sbase = smem_u32(sm);

    const int tid = threadIdx.x;
    const int wid = tid >> 5;
    const int lane = tid & 31;
    const int lq  = lane >> 2;   // 0..7
    const int lr  = lane & 3;    // 0..3

    const int row0 = blockIdx.y * 128;
    const int col0 = blockIdx.x * 128;

    const int m0 = (wid >> 1) * 32;   // warp m offset within tile
    const int n0 = (wid & 1) * 64;    // warp n offset within tile

    // per-chunk loader: 16B cp.async, 4 per thread per matrix
    auto load_chunk = [&](int kc, int stage) {
        const int k0 = kc * 32;
        const uint32_t st = sbase + (uint32_t)stage * STG_F * 4;
        #pragma unroll
        for (int i = 0; i < 4; i++) {
            const int c = tid + i * 256;       // 0..1023
            const int r = c >> 3;              // 0..127
            const int o = c & 7;               // 0..7 (16B units)
            const uint32_t so = (uint32_t)(r * ROWPAD * 4 + o * 16);
            const size_t ga = (size_t)(row0 + r) * DD + k0 + o * 4;
            const size_t gb = (size_t)(col0 + r) * DD + k0 + o * 4;
            cp16(st + 0 * MAT_F * 4 + so, &Ahi_g[ga]);
            cp16(st + 1 * MAT_F * 4 + so, &Alo_g[ga]);
            cp16(st + 2 * MAT_F * 4 + so, &Bhi_g[gb]);
            cp16(st + 3 * MAT_F * 4 + so, &Blo_g[gb]);
        }
        CP_COMMIT();
    };

    float acc[2][8][4];
    #pragma unroll
    for (int mt = 0; mt < 2; mt++)
        #pragma unroll
        for (int nt = 0; nt < 8; nt++)
            #pragma unroll
            for (int r = 0; r < 4; r++)
                acc[mt][nt][r] = 0.f;

    load_chunk(0, 0);
    load_chunk(1, 1);

    for (int kc = 0; kc < NCHUNK; kc++) {
        if (kc == NCHUNK - 1) { CP_WAIT0(); } else { CP_WAIT1(); }
        __syncthreads();

        const float* st  = sm + (kc & 1) * STG_F;
        const float* Ah = st;
        const float* Al = st + MAT_F;
        const float* Bh = st + 2 * MAT_F;
        const float* Bl = st + 3 * MAT_F;

        #pragma unroll
        for (int s = 0; s < 4; s++) {
            const int k = s * 8;
            uint32_t ahi[2][4], alo[2][4];
            #pragma unroll
            for (int mt = 0; mt < 2; mt++) {
                const int r = m0 + mt * 16 + lq;
                const int cb = k + lr;
                ahi[mt][0] = __float_as_uint(Ah[r * ROWPAD + cb]);
                ahi[mt][1] = __float_as_uint(Ah[(r + 8) * ROWPAD + cb]);
                ahi[mt][2] = __float_as_uint(Ah[r * ROWPAD + cb + 4]);
                ahi[mt][3] = __float_as_uint(Ah[(r + 8) * ROWPAD + cb + 4]);
                alo[mt][0] = __float_as_uint(Al[r * ROWPAD + cb]);
                alo[mt][1] = __float_as_uint(Al[(r + 8) * ROWPAD + cb]);
                alo[mt][2] = __float_as_uint(Al[r * ROWPAD + cb + 4]);
                alo[mt][3] = __float_as_uint(Al[(r + 8) * ROWPAD + cb + 4]);
            }
            #pragma unroll
            for (int nt = 0; nt < 8; nt++) {
                const int n = n0 + nt * 8 + lq;
                uint32_t bhi[2], blo[2];
                bhi[0] = __float_as_uint(Bh[n * ROWPAD + k + lr]);
                bhi[1] = __float_as_uint(Bh[n * ROWPAD + k + 4 + lr]);
                blo[0] = __float_as_uint(Bl[n * ROWPAD + k + lr]);
                blo[1] = __float_as_uint(Bl[n * ROWPAD + k + 4 + lr]);
                MMA_TF32(acc[0][nt], ahi[0], bhi);
                MMA_TF32(acc[1][nt], ahi[1], bhi);
                MMA_TF32(acc[0][nt], ahi[0], blo);
                MMA_TF32(acc[1][nt], ahi[1], blo);
                MMA_TF32(acc[0][nt], alo[0], bhi);
                MMA_TF32(acc[1][nt], alo[1], bhi);
            }
        }
        __syncthreads();
        if (kc + 2 < NCHUNK) load_chunk(kc + 2, kc & 1);
    }

    // Epilogue: D[m][n] layout: c0 -> (lq, 2*lr), c1 -> +1 col, c2/c3 -> row+8
    #pragma unroll
    for (int mt = 0; mt < 2; mt++) {
        const int rm = row0 + m0 + mt * 16 + lq;
        #pragma unroll
        for (int nt = 0; nt < 8; nt++) {
            const int cn = col0 + n0 + nt * 8 + 2 * lr;
            const float2 bv = *reinterpret_cast<const float2*>(&bias[cn]);
            float2 v0 = make_float2(acc[mt][nt][0] + bv.x, acc[mt][nt][1] + bv.y);
            float2 v1 = make_float2(acc[mt][nt][2] + bv.x, acc[mt][nt][3] + bv.y);
            *reinterpret_cast<float2*>(&C[(size_t)rm * DD + cn])       = v0;
            *reinterpret_cast<float2*>(&C[(size_t)(rm + 8) * DD + cn]) = v1;
        }
    }
}

// ---------------------------------------------------------------------------
// Kernel 2: attn[b,h,t,s] = temp[h] * sum_d Kh[d,t] * Vh[d,s]   (FFMA2)
// ---------------------------------------------------------------------------
__global__ __launch_bounds__(256) void attn_kernel(const float* __restrict__ temperature)
{
    extern __shared__ float smf[];
    float (*Ks)[128] = reinterpret_cast<float (*)[128]>(smf);          // [d][t]
    float (*Vs)[128] = reinterpret_cast<float (*)[128]>(smf + 64*128); // [d][s]

    const int tid = threadIdx.x;
    const int tx = tid & 15;
    const int ty = tid >> 4;
    const int bh = blockIdx.z;
    const int b  = bh >> 4;
    const int h  = bh & 15;
    const int t0 = blockIdx.y * 128;
    const int s0 = blockIdx.x * 128;

    const float* Kh = g_K + (size_t)b * TT * DD + (size_t)(h * DH) * DD;
    const float* Vh = g_V + (size_t)b * TT * DD + (size_t)(h * DH) * DD;

    #pragma unroll
    for (int i = 0; i < 8; i++) {
        const int idx = i * 256 + tid;
        const int d  = idx >> 5;
        const int c4 = (idx & 31) * 4;
        *reinterpret_cast<float4*>(&Ks[d][c4]) =
            *reinterpret_cast<const float4*>(&Kh[(size_t)d * DD + t0 + c4]);
        *reinterpret_cast<float4*>(&Vs[d][c4]) =
            *reinterpret_cast<const float4*>(&Vh[(size_t)d * DD + s0 + c4]);
    }
    __syncthreads();

    unsigned long long acc[4][8] = {};

    #pragma unroll 8
    for (int d = 0; d < 64; d++) {
        float4 a0 = *reinterpret_cast<const float4*>(&Ks[d][ty * 8]);
        float4 a1 = *reinterpret_cast<const float4*>(&Ks[d][ty * 8 + 4]);
        float4 b0 = *reinterpret_cast<const float4*>(&Vs[d][tx * 8]);
        float4 b1 = *reinterpret_cast<const float4*>(&Vs[d][tx * 8 + 4]);
        unsigned long long a2[4] = {pack2(a0.x, a0.y), pack2(a0.z, a0.w),
                                    pack2(a1.x, a1.y), pack2(a1.z, a1.w)};
        unsigned long long bb[8] = {dup2(b0.x), dup2(b0.y), dup2(b0.z), dup2(b0.w),
                                    dup2(b1.x), dup2(b1.y), dup2(b1.z), dup2(b1.w)};
        #pragma unroll
        for (int ip = 0; ip < 4; ip++)
            #pragma unroll
            for (int j = 0; j < 8; j++)
                ffma2(acc[ip][j], a2[ip], bb[j]);
    }

    const float tmp = temperature[h];
    float* Abase = g_A + ((size_t)bh * TT + t0) * TT + s0;
    #pragma unroll
    for (int ip = 0; ip < 4; ip++) {
        float r0[8], r1[8];
        #pragma unroll
        for (int j = 0; j < 8; j++) {
            float2 v = unpack2(acc[ip][j]);
            r0[j] = v.x * tmp;
            r1[j] = v.y * tmp;
        }
        float* p0 = &Abase[(size_t)(ty * 8 + 2 * ip) * TT + tx * 8];
        float* p1 = p0 + TT;
        *reinterpret_cast<float4*>(p0)     = make_float4(r0[0], r0[1], r0[2], r0[3]);
        *reinterpret_cast<float4*>(p0 + 4) = make_float4(r0[4], r0[5], r0[6], r0[7]);
        *reinterpret_cast<float4*>(p1)     = make_float4(r1[0], r1[1], r1[2], r1[3]);
        *reinterpret_cast<float4*>(p1 + 4) = make_float4(r1[4], r1[5], r1[6], r1[7]);
    }
}

// ---------------------------------------------------------------------------
// Kernel 3: row softmax over last dim of g_A.  One warp per 1024-elem row.
// ---------------------------------------------------------------------------
__global__ __launch_bounds__(256) void softmax_kernel()
{
    const int warp_in_block = threadIdx.x >> 5;
    const int lane = threadIdx.x & 31;
    const size_t row = (size_t)blockIdx.x * 8 + warp_in_block;

    float* rp = g_A + row * TT;

    float vals[32];
    float mx = -3.402823466e+38f;
    #pragma unroll
    for (int i = 0; i < 8; i++) {
        float4 v = *reinterpret_cast<const float4*>(&rp[(i * 32 + lane) * 4]);
        vals[i * 4 + 0] = v.x; vals[i * 4 + 1] = v.y;
        vals[i * 4 + 2] = v.z; vals[i * 4 + 3] = v.w;
        mx = fmaxf(mx, fmaxf(fmaxf(v.x, v.y), fmaxf(v.z, v.w)));
    }
    #pragma unroll
    for (int off = 16; off > 0; off >>= 1)
        mx = fmaxf(mx, __shfl_xor_sync(0xffffffffu, mx, off));

    float sum = 0.f;
    #pragma unroll
    for (int i = 0; i < 32; i++) {
        vals[i] = __expf(vals[i] - mx);
        sum += vals[i];
    }
    #pragma unroll
    for (int off = 16; off > 0; off >>= 1)
        sum += __shfl_xor_sync(0xffffffffu, sum, off);

    const float inv = 1.0f / sum;
    #pragma unroll
    for (int i = 0; i < 8; i++) {
        float4 v;
        v.x = vals[i * 4 + 0] * inv; v.y = vals[i * 4 + 1] * inv;
        v.z = vals[i * 4 + 2] * inv; v.w = vals[i * 4 + 3] * inv;
        *reinterpret_cast<float4*>(&rp[(i * 32 + lane) * 4]) = v;
    }
}

// ---------------------------------------------------------------------------
// Kernel 4: out rows [h*64, h*64+64) = Qh(64x1024) @ A_bh(1024x1024)  (FFMA2)
// ---------------------------------------------------------------------------
__global__ __launch_bounds__(256) void out_kernel(float* __restrict__ out)
{
    __shared__ float Qs[32][68];
    __shared__ float Ps[32][128];

    const int tid = threadIdx.x;
    const int tx = tid & 15;
    const int ty = tid >> 4;
    const int bh = blockIdx.z;
    const int b  = bh >> 4;
    const int h  = bh & 15;
    const int s0 = blockIdx.x * 128;

    const float* Qh  = g_Q + (size_t)b * TT * DD + (size_t)(h * DH) * DD;
    const float* Abh = g_A + (size_t)bh * TT * TT;

    unsigned long long acc[2][8] = {};

    for (int k0 = 0; k0 < TT; k0 += 32) {
        #pragma unroll
        for (int i = 0; i < 2; i++) {
            const int idx = i * 256 + tid;
            const int r  = idx >> 3;
            const int c4 = (idx & 7) * 4;
            float4 q = *reinterpret_cast<const float4*>(&Qh[(size_t)r * DD + k0 + c4]);
            Qs[c4 + 0][r] = q.x; Qs[c4 + 1][r] = q.y;
            Qs[c4 + 2][r] = q.z; Qs[c4 + 3][r] = q.w;
        }
        #pragma unroll
        for (int i = 0; i < 4; i++) {
            const int idx = i * 256 + tid;
            const int r  = idx >> 5;
            const int c4 = (idx & 31) * 4;
            *reinterpret_cast<float4*>(&Ps[r][c4]) =
                *reinterpret_cast<const float4*>(&Abh[(size_t)(k0 + r) * TT + s0 + c4]);
        }
        __syncthreads();

        #pragma unroll
        for (int k = 0; k < 32; k++) {
            float4 a  = *reinterpret_cast<const float4*>(&Qs[k][ty * 4]);
            float4 b0 = *reinterpret_cast<const float4*>(&Ps[k][tx * 8]);
            float4 b1 = *reinterpret_cast<const float4*>(&Ps[k][tx * 8 + 4]);
            unsigned long long a2[2] = {pack2(a.x, a.y), pack2(a.z, a.w)};
            unsigned long long bb[8] = {dup2(b0.x), dup2(b0.y), dup2(b0.z), dup2(b0.w),
                                        dup2(b1.x), dup2(b1.y), dup2(b1.z), dup2(b1.w)};
            #pragma unroll
            for (int ip = 0; ip < 2; ip++)
                #pragma unroll
                for (int j = 0; j < 8; j++)
                    ffma2(acc[ip][j], a2[ip], bb[j]);
        }
        __syncthreads();
    }

    float* orow = out + (size_t)b * TT * DD + (size_t)(h * DH) * DD;
    #pragma unroll
    for (int ip = 0; ip < 2; ip++) {
        float r0[8], r1[8];
        #pragma unroll
        for (int j = 0; j < 8; j++) {
            float2 v = unpack2(acc[ip][j]);
            r0[j] = v.x;
            r1[j] = v.y;
        }
        float* p0 = &orow[(size_t)(ty * 4 + 2 * ip) * DD + s0 + tx * 8];
        float* p1 = p0 + DD;
        *reinterpret_cast<float4*>(p0)     = make_float4(r0[0], r0[1], r0[2], r0[3]);
        *reinterpret_cast<float4*>(p0 + 4) = make_float4(r0[4], r0[5], r0[6], r0[7]);
        *reinterpret_cast<float4*>(p1)     = make_float4(r1[0], r1[1], r1[2], r1[3]);
        *reinterpret_cast<float4*>(p1 + 4) = make_float4(r1[4], r1[5], r1[6], r1[7]);
    }
}

// ---------------------------------------------------------------------------
extern "C" void kernel_launch(void* const* d_in, const int* in_sizes, int n_in,
                              void* d_out, int out_size)
{
    const float* x    = (const float*)d_in[0];
    const float* Wq   = (const float*)d_in[1];
    const float* bq   = (const float*)d_in[2];
    const float* Wk   = (const float*)d_in[3];
    const float* bk   = (const float*)d_in[4];
    const float* Wv   = (const float*)d_in[5];
    const float* bv   = (const float*)d_in[6];
    const float* temp = (const float*)d_in[7];
    float* out = (float*)d_out;

    static float* Qp = nullptr;
    static float* Kp = nullptr;
    static float* Vp = nullptr;
    static float* Xhi = nullptr;
    static float* Xlo = nullptr;
    static float* Wthi = nullptr;
    static float* Wtlo = nullptr;
    if (!Qp) {
        cudaGetSymbolAddress((void**)&Qp, g_Q);
        cudaGetSymbolAddress((void**)&Kp, g_K);
        cudaGetSymbolAddress((void**)&Vp, g_V);
        cudaGetSymbolAddress((void**)&Xhi, g_Xhi);
        cudaGetSymbolAddress((void**)&Xlo, g_Xlo);
        cudaGetSymbolAddress((void**)&Wthi, g_Wthi);
        cudaGetSymbolAddress((void**)&Wtlo, g_Wtlo);
        cudaFuncSetAttribute(attn_kernel,
                             cudaFuncAttributeMaxDynamicSharedMemorySize, 65536);
        cudaFuncSetAttribute(proj_mma_kernel,
                             cudaFuncAttributeMaxDynamicSharedMemorySize, PROJ_SMEM);
    }

    // Prep: tf32 hi/lo split of X; transposed hi/lo weights
    split_x_kernel<<<BT * DD / 1024, 256>>>(x);
    {
        dim3 tg(32, 32);
        dim3 tb(32, 8);
        wtrans_kernel<<<tg, tb>>>(Wq, 0);
        wtrans_kernel<<<tg, tb>>>(Wk, 1);
        wtrans_kernel<<<tg, tb>>>(Wv, 2);
    }

    // Projections on tensor cores (mma.sync 3xTF32)
    dim3 pgrid(DD / 128, BT / 128);   // 8 x 32 = 256 blocks
    proj_mma_kernel<<<pgrid, 256, PROJ_SMEM>>>(Xhi, Xlo, Wthi + 0 * (size_t)DD * DD, Wtlo + 0 * (size_t)DD * DD, bq, Qp);
    proj_mma_kernel<<<pgrid, 256, PROJ_SMEM>>>(Xhi, Xlo, Wthi + 1 * (size_t)DD * DD, Wtlo + 1 * (size_t)DD * DD, bk, Kp);
    proj_mma_kernel<<<pgrid, 256, PROJ_SMEM>>>(Xhi, Xlo, Wthi + 2 * (size_t)DD * DD, Wtlo + 2 * (size_t)DD * DD, bv, Vp);

    dim3 agrid(TT / 128, TT / 128, BB * HH);
    attn_kernel<<<agrid, 256, 65536>>>(temp);

    softmax_kernel<<<(BB * HH * TT) / 8, 256>>>();

    dim3 ogrid(TT / 128, 1, BB * HH);
    out_kernel<<<ogrid, 256>>>(out);
}